// round 5
// baseline (speedup 1.0000x reference)
#include <cuda_runtime.h>
#include <math.h>

#define NN 100000
#define EE 3200000
#define GG 64
#define LL 3

// ---- scratch (static device globals; no runtime allocation) ----
__device__ int   g_cnt[NN];
__device__ int   g_cur[NN];
__device__ int   g_off[NN + 1];
__device__ float g_dinv[NN];
__device__ unsigned long long g_edges[EE];   // low32: src idx, high32: norm bits
__device__ float4 g_xw4[(size_t)NN * 32];    // per-layer linear output [N,128]
__device__ float4 g_hjk4[(size_t)NN * 96];   // JK concat buffer [N,384]
__device__ float g_gsum[GG * 384];
__device__ int   g_gcnt[GG];

// ---------------------------------------------------------------
__global__ void __launch_bounds__(256) k_zero_nodes() {
    int i = blockIdx.x * blockDim.x + threadIdx.x;
    if (i < NN) { g_cnt[i] = 0; g_cur[i] = 0; }
}

__global__ void __launch_bounds__(256) k_count(const int* __restrict__ ei) {
    int i = blockIdx.x * blockDim.x + threadIdx.x;
    if (i < EE) {
        int c = ei[EE + i];               // col (destination), int32
        atomicAdd(&g_cnt[c], 1);
    }
}

// single-block exclusive scan of g_cnt -> g_off
__global__ void __launch_bounds__(1024) k_scan() {
    __shared__ int s[1024];
    const int ITEMS = (NN + 1023) / 1024;   // 98
    int t = threadIdx.x;
    int base = t * ITEMS;
    int local = 0;
    for (int i = 0; i < ITEMS; i++) {
        int idx = base + i;
        if (idx < NN) local += g_cnt[idx];
    }
    s[t] = local;
    __syncthreads();
    for (int o = 1; o < 1024; o <<= 1) {
        int v = (t >= o) ? s[t - o] : 0;
        __syncthreads();
        s[t] += v;
        __syncthreads();
    }
    int run = s[t] - local;   // exclusive prefix
    for (int i = 0; i < ITEMS; i++) {
        int idx = base + i;
        if (idx < NN) { g_off[idx] = run; run += g_cnt[idx]; }
    }
    if (t == 0) g_off[NN] = EE;
}

__global__ void __launch_bounds__(256) k_dinv() {
    int i = blockIdx.x * blockDim.x + threadIdx.x;
    if (i < NN) g_dinv[i] = rsqrtf((float)(g_cnt[i] + 1));   // deg includes self loop
}

__global__ void __launch_bounds__(256) k_scatter(const int* __restrict__ ei) {
    int i = blockIdx.x * blockDim.x + threadIdx.x;
    if (i < EE) {
        int r = ei[i];
        int c = ei[EE + i];
        int pos = g_off[c] + atomicAdd(&g_cur[c], 1);
        float nm = g_dinv[r] * g_dinv[c];
        g_edges[pos] = (unsigned long long)(unsigned)r |
                       ((unsigned long long)__float_as_uint(nm) << 32);
    }
}

// xw = h @ W_l  (two 64x64 blocks). 128 threads, 64 rows per block.
__global__ void __launch_bounds__(128) k_gemm(const float* __restrict__ x,
                                              const float* __restrict__ Wc, int l) {
    __shared__ float sW[8192];        // [p][k][j]
    __shared__ float sHT[128 * 8];    // [col][row] (transposed h tile, 8 rows)
    int t = threadIdx.x;
    const float* W = Wc + l * 8192;
    const float* in = (l == 0) ? x : ((const float*)g_hjk4 + (size_t)(l - 1) * 128);
    int stride = (l == 0) ? 128 : 384;
    float* xw = (float*)g_xw4;

    for (int idx = t; idx < 8192; idx += 128) sW[idx] = W[idx];

    int rowBase = blockIdx.x * 64;
    int p = t >> 6, jj = t & 63;
    const float* wp = sW + p * 4096 + jj;

    for (int grp = 0; grp < 8; grp++) {
        int r0 = rowBase + grp * 8;
        __syncthreads();   // protect sHT from previous-iteration readers (also covers sW load)
        float v[8];
#pragma unroll
        for (int rr = 0; rr < 8; rr++) {
            int r = r0 + rr;
            v[rr] = (r < NN) ? in[(size_t)r * stride + t] : 0.f;
        }
        ((float4*)sHT)[t * 2]     = make_float4(v[0], v[1], v[2], v[3]);
        ((float4*)sHT)[t * 2 + 1] = make_float4(v[4], v[5], v[6], v[7]);
        __syncthreads();

        float acc[8] = {0, 0, 0, 0, 0, 0, 0, 0};
        const float4* hcol = (const float4*)sHT + (size_t)(p * 64) * 2;
#pragma unroll
        for (int k = 0; k < 64; k++) {
            float w = wp[k * 64];
            float4 a  = hcol[k * 2];
            float4 b2 = hcol[k * 2 + 1];
            acc[0] += a.x  * w; acc[1] += a.y  * w; acc[2] += a.z  * w; acc[3] += a.w  * w;
            acc[4] += b2.x * w; acc[5] += b2.y * w; acc[6] += b2.z * w; acc[7] += b2.w * w;
        }
#pragma unroll
        for (int rr = 0; rr < 8; rr++) {
            int r = r0 + rr;
            if (r < NN) xw[(size_t)r * 128 + t] = acc[rr];
        }
    }
}

// aggregation + bias + BN + ReLU, fused. one warp per destination node.
__global__ void __launch_bounds__(256) k_agg(const float* __restrict__ bc,
                                             const float* __restrict__ gam,
                                             const float* __restrict__ bet,
                                             const float* __restrict__ mea,
                                             const float* __restrict__ var, int l) {
    int warp = (blockIdx.x * blockDim.x + threadIdx.x) >> 5;
    int lane = threadIdx.x & 31;
    if (warp >= NN) return;
    int node = warp;

    float dn = g_dinv[node];
    float self = dn * dn;
    float4 a = g_xw4[(size_t)node * 32 + lane];
    float4 acc = make_float4(a.x * self, a.y * self, a.z * self, a.w * self);

    int beg = g_off[node], end = g_off[node + 1];
    for (int e = beg; e < end; e++) {
        unsigned long long pe = g_edges[e];
        int src = (int)(pe & 0xffffffffu);
        float nm = __uint_as_float((unsigned)(pe >> 32));
        float4 v = g_xw4[(size_t)src * 32 + lane];
        acc.x += v.x * nm; acc.y += v.y * nm; acc.z += v.z * nm; acc.w += v.w * nm;
    }

    const float4* b4v = (const float4*)(bc  + l * 128);
    const float4* g4v = (const float4*)(gam + l * 128);
    const float4* e4v = (const float4*)(bet + l * 128);
    const float4* m4v = (const float4*)(mea + l * 128);
    const float4* v4v = (const float4*)(var + l * 128);
    float4 b4 = b4v[lane], g4 = g4v[lane], e4 = e4v[lane], m4 = m4v[lane], vv4 = v4v[lane];

    float4 o;
    o.x = fmaxf(0.f, (acc.x + b4.x - m4.x) * rsqrtf(vv4.x + 1e-5f) * g4.x + e4.x);
    o.y = fmaxf(0.f, (acc.y + b4.y - m4.y) * rsqrtf(vv4.y + 1e-5f) * g4.y + e4.y);
    o.z = fmaxf(0.f, (acc.z + b4.z - m4.z) * rsqrtf(vv4.z + 1e-5f) * g4.z + e4.z);
    o.w = fmaxf(0.f, (acc.w + b4.w - m4.w) * rsqrtf(vv4.w + 1e-5f) * g4.w + e4.w);

    g_hjk4[(size_t)node * 96 + l * 32 + lane] = o;
}

__global__ void __launch_bounds__(256) k_zero_pool() {
    int i = blockIdx.x * blockDim.x + threadIdx.x;
    if (i < GG * 384) g_gsum[i] = 0.f;
    if (i < GG)       g_gcnt[i] = 0;
}

// batch is sorted (int32): per-slab register accumulation, flush on graph change.
__global__ void __launch_bounds__(384) k_pool(const int* __restrict__ batch) {
    int f = threadIdx.x;               // 384 threads, one per feature
    const float* hjk = (const float*)g_hjk4;
    int n0 = blockIdx.x * 128;
    int n1 = n0 + 128; if (n1 > NN) n1 = NN;
    int prev = -1; float acc = 0.f; int cl = 0;
    for (int n = n0; n < n1; n++) {
        int g = batch[n];
        if (g != prev) {
            if (prev >= 0) {
                atomicAdd(&g_gsum[prev * 384 + f], acc);
                if (f == 0) atomicAdd(&g_gcnt[prev], cl);
            }
            prev = g; acc = 0.f; cl = 0;
        }
        acc += hjk[(size_t)n * 384 + f];
        cl++;
    }
    if (prev >= 0) {
        atomicAdd(&g_gsum[prev * 384 + f], acc);
        if (f == 0) atomicAdd(&g_gcnt[prev], cl);
    }
}

// mean -> FC1 + ReLU -> FC2 -> log_softmax. one block per graph.
__global__ void __launch_bounds__(128) k_head(const float* __restrict__ W1,
                                              const float* __restrict__ b1,
                                              const float* __restrict__ W2,
                                              const float* __restrict__ b2,
                                              float* __restrict__ out) {
    __shared__ float sp[384];
    __shared__ float r0s[128], r1s[128];
    int g = blockIdx.x, j = threadIdx.x;   // 128 threads
    float c = (float)g_gcnt[g]; if (c < 1.f) c = 1.f;
    float inv = 1.f / c;
    for (int idx = j; idx < 384; idx += 128) sp[idx] = g_gsum[g * 384 + idx] * inv;
    __syncthreads();
    float acc = b1[j];
    for (int k = 0; k < 384; k++) acc += sp[k] * W1[k * 128 + j];
    float z = fmaxf(acc, 0.f);
    r0s[j] = z * W2[j * 2 + 0];
    r1s[j] = z * W2[j * 2 + 1];
    __syncthreads();
    for (int s = 64; s > 0; s >>= 1) {
        if (j < s) { r0s[j] += r0s[j + s]; r1s[j] += r1s[j + s]; }
        __syncthreads();
    }
    if (j == 0) {
        float z0 = r0s[0] + b2[0], z1 = r1s[0] + b2[1];
        float m = fmaxf(z0, z1);
        float lse = m + logf(expf(z0 - m) + expf(z1 - m));
        out[g * 2 + 0] = z0 - lse;
        out[g * 2 + 1] = z1 - lse;
    }
}

// ---------------------------------------------------------------
extern "C" void kernel_launch(void* const* d_in, const int* in_sizes, int n_in,
                              void* d_out, int out_size) {
    const float* x     = (const float*)d_in[0];
    const int*   ei    = (const int*)d_in[1];      // int32 (JAX x64 disabled)
    const int*   batch = (const int*)d_in[2];      // int32
    const float* Wc    = (const float*)d_in[3];
    const float* bc    = (const float*)d_in[4];
    const float* gam   = (const float*)d_in[5];
    const float* bet   = (const float*)d_in[6];
    const float* mea   = (const float*)d_in[7];
    const float* var   = (const float*)d_in[8];
    const float* W1    = (const float*)d_in[9];
    const float* b1    = (const float*)d_in[10];
    const float* W2    = (const float*)d_in[11];
    const float* b2    = (const float*)d_in[12];
    float* out = (float*)d_out;

    k_zero_nodes<<<(NN + 255) / 256, 256>>>();
    k_count<<<(EE + 255) / 256, 256>>>(ei);
    k_scan<<<1, 1024>>>();
    k_dinv<<<(NN + 255) / 256, 256>>>();
    k_scatter<<<(EE + 255) / 256, 256>>>(ei);

    for (int l = 0; l < LL; l++) {
        k_gemm<<<(NN + 63) / 64, 128>>>(x, Wc, l);
        k_agg<<<(NN * 32 + 255) / 256, 256>>>(bc, gam, bet, mea, var, l);
    }

    k_zero_pool<<<(GG * 384 + 255) / 256, 256>>>();
    k_pool<<<(NN + 127) / 128, 384>>>(batch);
    k_head<<<GG, 128>>>(W1, b1, W2, b2, out);
}

// round 6
// speedup vs baseline: 1.0738x; 1.0738x over previous
#include <cuda_runtime.h>
#include <cuda_fp16.h>
#include <math.h>

#define NN 100000
#define EE 3200000
#define GG 64
#define LL 3

// ---- scratch (static device globals; no runtime allocation) ----
__device__ int   g_cnt[NN];
__device__ int   g_cur[NN];
__device__ int   g_off[NN + 1];
__device__ float g_dinv[NN];
__device__ unsigned long long g_edges[EE];   // low32: src idx, high32: norm bits
__device__ __half g_xwh[(size_t)NN * 128];   // per-layer linear output [N,128] fp16
__device__ float4 g_hjk4[(size_t)NN * 96];   // JK concat buffer [N,384] fp32
__device__ float g_gsum[GG * 384];
__device__ int   g_gcnt[GG];

// ---------------------------------------------------------------
__global__ void __launch_bounds__(256) k_zero_nodes() {
    int i = blockIdx.x * blockDim.x + threadIdx.x;
    if (i < NN) { g_cnt[i] = 0; g_cur[i] = 0; }
}

__global__ void __launch_bounds__(256) k_count(const int* __restrict__ ei) {
    int i = blockIdx.x * blockDim.x + threadIdx.x;
    if (i < EE) {
        int c = ei[EE + i];               // col (destination), int32
        atomicAdd(&g_cnt[c], 1);
    }
}

// single-block exclusive scan of g_cnt -> g_off
__global__ void __launch_bounds__(1024) k_scan() {
    __shared__ int s[1024];
    const int ITEMS = (NN + 1023) / 1024;   // 98
    int t = threadIdx.x;
    int base = t * ITEMS;
    int local = 0;
    for (int i = 0; i < ITEMS; i++) {
        int idx = base + i;
        if (idx < NN) local += g_cnt[idx];
    }
    s[t] = local;
    __syncthreads();
    for (int o = 1; o < 1024; o <<= 1) {
        int v = (t >= o) ? s[t - o] : 0;
        __syncthreads();
        s[t] += v;
        __syncthreads();
    }
    int run = s[t] - local;   // exclusive prefix
    for (int i = 0; i < ITEMS; i++) {
        int idx = base + i;
        if (idx < NN) { g_off[idx] = run; run += g_cnt[idx]; }
    }
    if (t == 0) g_off[NN] = EE;
}

__global__ void __launch_bounds__(256) k_dinv() {
    int i = blockIdx.x * blockDim.x + threadIdx.x;
    if (i < NN) g_dinv[i] = rsqrtf((float)(g_cnt[i] + 1));   // deg includes self loop
}

__global__ void __launch_bounds__(256) k_scatter(const int* __restrict__ ei) {
    int i = blockIdx.x * blockDim.x + threadIdx.x;
    if (i < EE) {
        int r = ei[i];
        int c = ei[EE + i];
        int pos = g_off[c] + atomicAdd(&g_cur[c], 1);
        float nm = g_dinv[r] * g_dinv[c];
        g_edges[pos] = (unsigned long long)(unsigned)r |
                       ((unsigned long long)__float_as_uint(nm) << 32);
    }
}

// xw = h @ W_l  (two 64x64 blocks). 128 threads, 64 rows per block. fp16 output.
__global__ void __launch_bounds__(128) k_gemm(const float* __restrict__ x,
                                              const float* __restrict__ Wc, int l) {
    __shared__ float sW[8192];        // [p][k][j]
    __shared__ float sHT[128 * 8];    // [col][row] (transposed h tile, 8 rows)
    int t = threadIdx.x;
    const float* W = Wc + l * 8192;
    const float* in = (l == 0) ? x : ((const float*)g_hjk4 + (size_t)(l - 1) * 128);
    int stride = (l == 0) ? 128 : 384;

    for (int idx = t; idx < 8192; idx += 128) sW[idx] = W[idx];

    int rowBase = blockIdx.x * 64;
    int p = t >> 6, jj = t & 63;
    const float* wp = sW + p * 4096 + jj;

    for (int grp = 0; grp < 8; grp++) {
        int r0 = rowBase + grp * 8;
        __syncthreads();   // protect sHT from previous-iteration readers (also covers sW load)
        float v[8];
#pragma unroll
        for (int rr = 0; rr < 8; rr++) {
            int r = r0 + rr;
            v[rr] = (r < NN) ? in[(size_t)r * stride + t] : 0.f;
        }
        ((float4*)sHT)[t * 2]     = make_float4(v[0], v[1], v[2], v[3]);
        ((float4*)sHT)[t * 2 + 1] = make_float4(v[4], v[5], v[6], v[7]);
        __syncthreads();

        float acc[8] = {0, 0, 0, 0, 0, 0, 0, 0};
        const float4* hcol = (const float4*)sHT + (size_t)(p * 64) * 2;
#pragma unroll
        for (int k = 0; k < 64; k++) {
            float w = wp[k * 64];
            float4 a  = hcol[k * 2];
            float4 b2 = hcol[k * 2 + 1];
            acc[0] += a.x  * w; acc[1] += a.y  * w; acc[2] += a.z  * w; acc[3] += a.w  * w;
            acc[4] += b2.x * w; acc[5] += b2.y * w; acc[6] += b2.z * w; acc[7] += b2.w * w;
        }
#pragma unroll
        for (int rr = 0; rr < 8; rr++) {
            int r = r0 + rr;
            if (r < NN) g_xwh[(size_t)r * 128 + t] = __float2half(acc[rr]);
        }
    }
}

// aggregation + bias + BN + ReLU, fused. one warp per destination node.
// xw rows are fp16 (256B): lane owns 4 features via one uint2 (2x half2).
__global__ void __launch_bounds__(256) k_agg(const float* __restrict__ bc,
                                             const float* __restrict__ gam,
                                             const float* __restrict__ bet,
                                             const float* __restrict__ mea,
                                             const float* __restrict__ var, int l) {
    int warp = (blockIdx.x * blockDim.x + threadIdx.x) >> 5;
    int lane = threadIdx.x & 31;
    if (warp >= NN) return;
    int node = warp;

    const uint2* xw2 = (const uint2*)g_xwh;   // 32 uint2 per 128-half row

    float dn = g_dinv[node];
    float self = dn * dn;
    uint2 ra = xw2[(size_t)node * 32 + lane];
    float2 a0 = __half22float2(*(const half2*)&ra.x);
    float2 a1 = __half22float2(*(const half2*)&ra.y);
    float4 acc = make_float4(a0.x * self, a0.y * self, a1.x * self, a1.y * self);

    int beg = g_off[node], end = g_off[node + 1];
    for (int e = beg; e < end; e++) {
        unsigned long long pe = g_edges[e];
        int src = (int)(pe & 0xffffffffu);
        float nm = __uint_as_float((unsigned)(pe >> 32));
        uint2 rv = xw2[(size_t)src * 32 + lane];
        float2 v0 = __half22float2(*(const half2*)&rv.x);
        float2 v1 = __half22float2(*(const half2*)&rv.y);
        acc.x += v0.x * nm; acc.y += v0.y * nm; acc.z += v1.x * nm; acc.w += v1.y * nm;
    }

    const float4* b4v = (const float4*)(bc  + l * 128);
    const float4* g4v = (const float4*)(gam + l * 128);
    const float4* e4v = (const float4*)(bet + l * 128);
    const float4* m4v = (const float4*)(mea + l * 128);
    const float4* v4v = (const float4*)(var + l * 128);
    float4 b4 = b4v[lane], g4 = g4v[lane], e4 = e4v[lane], m4 = m4v[lane], vv4 = v4v[lane];

    float4 o;
    o.x = fmaxf(0.f, (acc.x + b4.x - m4.x) * rsqrtf(vv4.x + 1e-5f) * g4.x + e4.x);
    o.y = fmaxf(0.f, (acc.y + b4.y - m4.y) * rsqrtf(vv4.y + 1e-5f) * g4.y + e4.y);
    o.z = fmaxf(0.f, (acc.z + b4.z - m4.z) * rsqrtf(vv4.z + 1e-5f) * g4.z + e4.z);
    o.w = fmaxf(0.f, (acc.w + b4.w - m4.w) * rsqrtf(vv4.w + 1e-5f) * g4.w + e4.w);

    g_hjk4[(size_t)node * 96 + l * 32 + lane] = o;
}

__global__ void __launch_bounds__(256) k_zero_pool() {
    int i = blockIdx.x * blockDim.x + threadIdx.x;
    if (i < GG * 384) g_gsum[i] = 0.f;
    if (i < GG)       g_gcnt[i] = 0;
}

// batch is sorted (int32): per-slab register accumulation, flush on graph change.
__global__ void __launch_bounds__(384) k_pool(const int* __restrict__ batch) {
    int f = threadIdx.x;               // 384 threads, one per feature
    const float* hjk = (const float*)g_hjk4;
    int n0 = blockIdx.x * 128;
    int n1 = n0 + 128; if (n1 > NN) n1 = NN;
    int prev = -1; float acc = 0.f; int cl = 0;
    for (int n = n0; n < n1; n++) {
        int g = batch[n];
        if (g != prev) {
            if (prev >= 0) {
                atomicAdd(&g_gsum[prev * 384 + f], acc);
                if (f == 0) atomicAdd(&g_gcnt[prev], cl);
            }
            prev = g; acc = 0.f; cl = 0;
        }
        acc += hjk[(size_t)n * 384 + f];
        cl++;
    }
    if (prev >= 0) {
        atomicAdd(&g_gsum[prev * 384 + f], acc);
        if (f == 0) atomicAdd(&g_gcnt[prev], cl);
    }
}

// mean -> FC1 + ReLU -> FC2 -> log_softmax. one block per graph.
__global__ void __launch_bounds__(128) k_head(const float* __restrict__ W1,
                                              const float* __restrict__ b1,
                                              const float* __restrict__ W2,
                                              const float* __restrict__ b2,
                                              float* __restrict__ out) {
    __shared__ float sp[384];
    __shared__ float r0s[128], r1s[128];
    int g = blockIdx.x, j = threadIdx.x;   // 128 threads
    float c = (float)g_gcnt[g]; if (c < 1.f) c = 1.f;
    float inv = 1.f / c;
    for (int idx = j; idx < 384; idx += 128) sp[idx] = g_gsum[g * 384 + idx] * inv;
    __syncthreads();
    float acc = b1[j];
    for (int k = 0; k < 384; k++) acc += sp[k] * W1[k * 128 + j];
    float z = fmaxf(acc, 0.f);
    r0s[j] = z * W2[j * 2 + 0];
    r1s[j] = z * W2[j * 2 + 1];
    __syncthreads();
    for (int s = 64; s > 0; s >>= 1) {
        if (j < s) { r0s[j] += r0s[j + s]; r1s[j] += r1s[j + s]; }
        __syncthreads();
    }
    if (j == 0) {
        float z0 = r0s[0] + b2[0], z1 = r1s[0] + b2[1];
        float m = fmaxf(z0, z1);
        float lse = m + logf(expf(z0 - m) + expf(z1 - m));
        out[g * 2 + 0] = z0 - lse;
        out[g * 2 + 1] = z1 - lse;
    }
}

// ---------------------------------------------------------------
extern "C" void kernel_launch(void* const* d_in, const int* in_sizes, int n_in,
                              void* d_out, int out_size) {
    const float* x     = (const float*)d_in[0];
    const int*   ei    = (const int*)d_in[1];      // int32 (JAX x64 disabled)
    const int*   batch = (const int*)d_in[2];      // int32
    const float* Wc    = (const float*)d_in[3];
    const float* bc    = (const float*)d_in[4];
    const float* gam   = (const float*)d_in[5];
    const float* bet   = (const float*)d_in[6];
    const float* mea   = (const float*)d_in[7];
    const float* var   = (const float*)d_in[8];
    const float* W1    = (const float*)d_in[9];
    const float* b1    = (const float*)d_in[10];
    const float* W2    = (const float*)d_in[11];
    const float* b2    = (const float*)d_in[12];
    float* out = (float*)d_out;

    k_zero_nodes<<<(NN + 255) / 256, 256>>>();
    k_count<<<(EE + 255) / 256, 256>>>(ei);
    k_scan<<<1, 1024>>>();
    k_dinv<<<(NN + 255) / 256, 256>>>();
    k_scatter<<<(EE + 255) / 256, 256>>>(ei);

    for (int l = 0; l < LL; l++) {
        k_gemm<<<(NN + 63) / 64, 128>>>(x, Wc, l);
        k_agg<<<(NN * 32 + 255) / 256, 256>>>(bc, gam, bet, mea, var, l);
    }

    k_zero_pool<<<(GG * 384 + 255) / 256, 256>>>();
    k_pool<<<(NN + 127) / 128, 384>>>(batch);
    k_head<<<GG, 128>>>(W1, b1, W2, b2, out);
}